// round 1
// baseline (speedup 1.0000x reference)
#include <cuda_runtime.h>
#include <math.h>

#define NN 100000
#define EE 1600000

// ---------------- static device scratch (no allocations allowed) ----------------
__device__ float g_bufA[NN * 64];
__device__ float g_bufB[NN * 64];
__device__ int   g_csr[EE];
__device__ int   g_rowptr[NN + 1];
__device__ int   g_next[NN];
__device__ int   g_counts[NN];
__device__ float g_dinv[NN];
__device__ float g_stat[4 * 64];   // sum1, sumsq1, sum2, sumsq2
__device__ float g_aff[4 * 64];    // scale1, shift1, scale2, shift2

// ---------------- zero counts + BN stats ----------------
__global__ void zero_kernel(int* counts, float* stat, int n) {
    int i = blockIdx.x * blockDim.x + threadIdx.x;
    if (i < n) counts[i] = 0;
    if (i < 4 * 64) stat[i] = 0.0f;
}

// ---------------- count in-degree (by dst) ----------------
__global__ void count_kernel(const int* __restrict__ dst, int* counts, int e) {
    int i = blockIdx.x * blockDim.x + threadIdx.x;
    if (i < e) atomicAdd(&counts[dst[i]], 1);
}

// ---------------- single-block exclusive scan -> rowptr, next, dinv ----------------
__global__ void scan_kernel(const int* __restrict__ counts, int* rowptr, int* nextp,
                            float* dinv, int n) {
    __shared__ int sdata[1024];
    __shared__ int carry_s;
    int t = threadIdx.x;
    if (t == 0) carry_s = 0;
    __syncthreads();
    for (int base = 0; base < n; base += 1024) {
        int i = base + t;
        int v = (i < n) ? counts[i] : 0;
        sdata[t] = v;
        __syncthreads();
        #pragma unroll
        for (int off = 1; off < 1024; off <<= 1) {
            int a = (t >= off) ? sdata[t - off] : 0;
            __syncthreads();
            sdata[t] += a;
            __syncthreads();
        }
        int incl = sdata[t];
        int carry = carry_s;
        if (i < n) {
            int rp = carry + incl - v;
            rowptr[i] = rp;
            nextp[i]  = rp;
            dinv[i]   = rsqrtf((float)(v + 1));   // deg includes self loop, always > 0
        }
        __syncthreads();
        if (t == 1023) carry_s = carry + incl;
        __syncthreads();
    }
    if (t == 0) rowptr[n] = carry_s;
}

// ---------------- scatter edges into CSR by dst ----------------
__global__ void fill_kernel(const int* __restrict__ src, const int* __restrict__ dst,
                            int* nextp, int* csr, int e) {
    int i = blockIdx.x * blockDim.x + threadIdx.x;
    if (i < e) {
        int d = dst[i];
        int p = atomicAdd(&nextp[d], 1);
        csr[p] = src[i];
    }
}

// ---------------- GEMM: Y[N,64] = act(X)[N,CIN] @ W^T + b ----------------
// act = identity (layer 1) or fused BN affine + ReLU (layers 2,3)
template <int CIN, bool BN>
__global__ void gemm_kernel(const float* __restrict__ X, const float* __restrict__ W,
                            const float* __restrict__ bias,
                            const float* __restrict__ scale, const float* __restrict__ shift,
                            float* __restrict__ Y, int n) {
    constexpr int R   = (CIN == 128) ? 16 : 32;   // rows per block (smem budget)
    constexpr int OPT = 64 * R / 256;             // outputs per thread (4 or 8)
    constexpr int G   = 64 / OPT;                 // output groups per row

    __shared__ float Wsm[CIN * 68];               // [k][o], padded to 68 (16B-aligned rows)
    __shared__ float Xsm[R * (CIN + 1)];

    int t = threadIdx.x;
    // W: [64, CIN] row-major; coalesced read, transposed store
    for (int idx = t; idx < CIN * 64; idx += 256) {
        int o = idx / CIN, k = idx % CIN;
        Wsm[k * 68 + o] = W[idx];
    }
    int row0 = blockIdx.x * R;
    for (int idx = t; idx < R * CIN; idx += 256) {
        int r = idx / CIN, k = idx % CIN;
        int gr = row0 + r;
        float v = (gr < n) ? X[gr * CIN + k] : 0.0f;
        if (BN) v = fmaxf(fmaf(v, scale[k], shift[k]), 0.0f);
        Xsm[r * (CIN + 1) + k] = v;
    }
    __syncthreads();

    int r = t / G;
    int g = t % G;
    float acc[OPT];
    #pragma unroll
    for (int j = 0; j < OPT; j++) acc[j] = __ldg(&bias[g * OPT + j]);

    #pragma unroll 4
    for (int k = 0; k < CIN; k++) {
        float xv = Xsm[r * (CIN + 1) + k];
        const float4* wp = reinterpret_cast<const float4*>(&Wsm[k * 68 + g * OPT]);
        #pragma unroll
        for (int j4 = 0; j4 < OPT / 4; j4++) {
            float4 w = wp[j4];
            acc[j4 * 4 + 0] = fmaf(xv, w.x, acc[j4 * 4 + 0]);
            acc[j4 * 4 + 1] = fmaf(xv, w.y, acc[j4 * 4 + 1]);
            acc[j4 * 4 + 2] = fmaf(xv, w.z, acc[j4 * 4 + 2]);
            acc[j4 * 4 + 3] = fmaf(xv, w.w, acc[j4 * 4 + 3]);
        }
    }
    int gr = row0 + r;
    if (gr < n) {
        float4* yo = reinterpret_cast<float4*>(&Y[gr * 64 + g * OPT]);
        #pragma unroll
        for (int j4 = 0; j4 < OPT / 4; j4++) {
            float4 v;
            v.x = acc[j4 * 4 + 0]; v.y = acc[j4 * 4 + 1];
            v.z = acc[j4 * 4 + 2]; v.w = acc[j4 * 4 + 3];
            yo[j4] = v;
        }
    }
}

// ---------------- aggregation: out[i] = dinv[i]*(dinv[i]*Y[i] + sum_j dinv[j]*Y[j]) ----------------
// warp per node; lane handles features lane and lane+32.
// Optionally fused row-wise log_softmax for the final layer.
template <bool LOGSM>
__global__ void agg_kernel(const float* __restrict__ Y,
                           const int* __restrict__ rowptr, const int* __restrict__ csr,
                           const float* __restrict__ dinv,
                           float* __restrict__ out, int n) {
    int warp = (blockIdx.x * blockDim.x + threadIdx.x) >> 5;
    int lane = threadIdx.x & 31;
    if (warp >= n) return;
    int i = warp;
    float di = __ldg(&dinv[i]);
    float a0 = di * __ldg(&Y[i * 64 + lane]);
    float a1 = di * __ldg(&Y[i * 64 + 32 + lane]);
    int s = __ldg(&rowptr[i]);
    int e = __ldg(&rowptr[i + 1]);
    int p = s;
    for (; p + 1 < e; p += 2) {
        int j0 = __ldg(&csr[p]);
        int j1 = __ldg(&csr[p + 1]);
        float w0 = __ldg(&dinv[j0]);
        float w1 = __ldg(&dinv[j1]);
        a0 = fmaf(w0, __ldg(&Y[j0 * 64 + lane]),      a0);
        a1 = fmaf(w0, __ldg(&Y[j0 * 64 + 32 + lane]), a1);
        a0 = fmaf(w1, __ldg(&Y[j1 * 64 + lane]),      a0);
        a1 = fmaf(w1, __ldg(&Y[j1 * 64 + 32 + lane]), a1);
    }
    if (p < e) {
        int j0 = __ldg(&csr[p]);
        float w0 = __ldg(&dinv[j0]);
        a0 = fmaf(w0, __ldg(&Y[j0 * 64 + lane]),      a0);
        a1 = fmaf(w0, __ldg(&Y[j0 * 64 + 32 + lane]), a1);
    }
    a0 *= di;
    a1 *= di;
    if (!LOGSM) {
        out[i * 64 + lane]      = a0;
        out[i * 64 + 32 + lane] = a1;
    } else {
        float m = fmaxf(a0, a1);
        #pragma unroll
        for (int off = 16; off > 0; off >>= 1)
            m = fmaxf(m, __shfl_xor_sync(0xFFFFFFFFu, m, off));
        float sum = expf(a0 - m) + expf(a1 - m);
        #pragma unroll
        for (int off = 16; off > 0; off >>= 1)
            sum += __shfl_xor_sync(0xFFFFFFFFu, sum, off);
        float lz = m + logf(sum);
        out[i * 64 + lane]      = a0 - lz;
        out[i * 64 + 32 + lane] = a1 - lz;
    }
}

// ---------------- BN column stats ----------------
__global__ void bnstats_kernel(const float* __restrict__ A, float* sums, float* sumsq, int n) {
    int c  = threadIdx.x & 63;
    int rg = threadIdx.x >> 6;   // 0..3
    float s = 0.0f, s2 = 0.0f;
    for (int r = blockIdx.x * 4 + rg; r < n; r += gridDim.x * 4) {
        float v = A[r * 64 + c];
        s += v;
        s2 = fmaf(v, v, s2);
    }
    __shared__ float sh[256], sh2[256];
    sh[threadIdx.x] = s; sh2[threadIdx.x] = s2;
    __syncthreads();
    if (threadIdx.x < 64) {
        s  = sh[threadIdx.x]  + sh[threadIdx.x + 64]  + sh[threadIdx.x + 128]  + sh[threadIdx.x + 192];
        s2 = sh2[threadIdx.x] + sh2[threadIdx.x + 64] + sh2[threadIdx.x + 128] + sh2[threadIdx.x + 192];
        atomicAdd(&sums[c],  s);
        atomicAdd(&sumsq[c], s2);
    }
}

// ---------------- BN finalize: affine = gamma*rsqrt(var+eps), shift = beta - mean*affine ----------------
__global__ void bnfin_kernel(const float* __restrict__ stat, const float* __restrict__ gam,
                             const float* __restrict__ bet, float* aff, int n) {
    int c = threadIdx.x;
    if (c < 64) {
        float mean = stat[c] / (float)n;
        float var  = stat[64 + c] / (float)n - mean * mean;
        float rs   = rsqrtf(var + 1e-5f);
        float sc   = rs * gam[c];
        aff[c]      = sc;
        aff[64 + c] = bet[c] - mean * sc;
    }
}

// ---------------- host launcher ----------------
extern "C" void kernel_launch(void* const* d_in, const int* in_sizes, int n_in,
                              void* d_out, int out_size) {
    const float* x   = (const float*)d_in[0];
    const int*   ei  = (const int*)  d_in[1];
    const float* W1  = (const float*)d_in[2];
    const float* b1  = (const float*)d_in[3];
    const float* ga1 = (const float*)d_in[4];
    const float* be1 = (const float*)d_in[5];
    const float* W2  = (const float*)d_in[6];
    const float* b2  = (const float*)d_in[7];
    const float* ga2 = (const float*)d_in[8];
    const float* be2 = (const float*)d_in[9];
    const float* W3  = (const float*)d_in[10];
    const float* b3  = (const float*)d_in[11];
    float* out = (float*)d_out;

    int N = in_sizes[0] / 128;
    int E = in_sizes[1] / 2;
    const int* src = ei;
    const int* dst = ei + E;

    void* p;
    cudaGetSymbolAddress(&p, g_bufA);   float* bufA   = (float*)p;
    cudaGetSymbolAddress(&p, g_bufB);   float* bufB   = (float*)p;
    cudaGetSymbolAddress(&p, g_csr);    int*   csr    = (int*)p;
    cudaGetSymbolAddress(&p, g_rowptr); int*   rowptr = (int*)p;
    cudaGetSymbolAddress(&p, g_next);   int*   nextp  = (int*)p;
    cudaGetSymbolAddress(&p, g_counts); int*   counts = (int*)p;
    cudaGetSymbolAddress(&p, g_dinv);   float* dinv   = (float*)p;
    cudaGetSymbolAddress(&p, g_stat);   float* stat   = (float*)p;
    cudaGetSymbolAddress(&p, g_aff);    float* aff    = (float*)p;

    int gridN = (N + 255) / 256;
    int gridE = (E + 255) / 256;
    int gridW = (N * 32 + 255) / 256;   // warp per node

    // CSR build (reused by all 3 layers)
    zero_kernel<<<gridN, 256>>>(counts, stat, N);
    count_kernel<<<gridE, 256>>>(dst, counts, E);
    scan_kernel<<<1, 1024>>>(counts, rowptr, nextp, dinv, N);
    fill_kernel<<<gridE, 256>>>(src, dst, nextp, csr, E);

    // layer 1
    gemm_kernel<128, false><<<(N + 15) / 16, 256>>>(x, W1, b1, nullptr, nullptr, bufA, N);
    agg_kernel<false><<<gridW, 256>>>(bufA, rowptr, csr, dinv, bufB, N);
    bnstats_kernel<<<512, 256>>>(bufB, stat, stat + 64, N);
    bnfin_kernel<<<1, 64>>>(stat, ga1, be1, aff, N);

    // layer 2 (BN1+ReLU fused into GEMM input)
    gemm_kernel<64, true><<<(N + 31) / 32, 256>>>(bufB, W2, b2, aff, aff + 64, bufA, N);
    agg_kernel<false><<<gridW, 256>>>(bufA, rowptr, csr, dinv, bufB, N);
    bnstats_kernel<<<512, 256>>>(bufB, stat + 128, stat + 192, N);
    bnfin_kernel<<<1, 64>>>(stat + 128, ga2, be2, aff + 128, N);

    // layer 3 (BN2+ReLU fused into GEMM input) + fused log_softmax
    gemm_kernel<64, true><<<(N + 31) / 32, 256>>>(bufB, W3, b3, aff + 128, aff + 192, bufA, N);
    agg_kernel<true><<<gridW, 256>>>(bufA, rowptr, csr, dinv, out, N);
}

// round 2
// speedup vs baseline: 2.2901x; 2.2901x over previous
#include <cuda_runtime.h>
#include <math.h>

#define NN 100000
#define EE 1600000

// ---------------- static device scratch ----------------
__device__ float g_bufA[NN * 64];
__device__ float g_bufB[NN * 64];
__device__ int   g_csr[EE];
__device__ int   g_rowptr[NN + 1];
__device__ int   g_next[NN];
__device__ int   g_counts[NN];
__device__ float g_dinv[NN];
__device__ float g_stat[4 * 64];
__device__ float g_aff[4 * 64];
__device__ int   g_bsum[1024];
__device__ int   g_boff[1024];

// ---------------- packed f32x2 helpers ----------------
__device__ __forceinline__ unsigned long long pack2(float x, float y) {
    unsigned long long r;
    asm("mov.b64 %0, {%1, %2};" : "=l"(r) : "f"(x), "f"(y));
    return r;
}
__device__ __forceinline__ unsigned long long pack2s(float x) {
    unsigned long long r;
    asm("mov.b64 %0, {%1, %1};" : "=l"(r) : "f"(x));
    return r;
}
__device__ __forceinline__ void unpack2(unsigned long long v, float& x, float& y) {
    asm("mov.b64 {%0, %1}, %2;" : "=f"(x), "=f"(y) : "l"(v));
}
__device__ __forceinline__ void ffma2(unsigned long long& a, unsigned long long x,
                                      unsigned long long w) {
#if defined(__CUDA_ARCH__) && (__CUDA_ARCH__ >= 1000)
    asm("fma.rn.f32x2 %0, %1, %2, %0;" : "+l"(a) : "l"(x), "l"(w));
#else
    float ax, ay, xx, xy, wx, wy;
    unpack2(a, ax, ay); unpack2(x, xx, xy); unpack2(w, wx, wy);
    a = pack2(fmaf(xx, wx, ax), fmaf(xy, wy, ay));
#endif
}

// ---------------- zero counts + BN stats ----------------
__global__ void zero_kernel(int* counts, float* stat, int n) {
    int i = blockIdx.x * blockDim.x + threadIdx.x;
    if (i < n) counts[i] = 0;
    if (i < 4 * 64) stat[i] = 0.0f;
}

// ---------------- count in-degree ----------------
__global__ void count_kernel(const int* __restrict__ dst, int* counts, int e) {
    int i = blockIdx.x * blockDim.x + threadIdx.x;
    if (i < e) atomicAdd(&counts[dst[i]], 1);
}

// ---------------- two-level scan ----------------
__global__ void bsum_kernel(const int* __restrict__ counts, int* bsum, int n) {
    __shared__ int sh[8];
    int base = blockIdx.x * 1024;
    int t = threadIdx.x;
    int s = 0;
    #pragma unroll
    for (int j = 0; j < 4; j++) {
        int i = base + t + j * 256;
        if (i < n) s += counts[i];
    }
    #pragma unroll
    for (int o = 16; o > 0; o >>= 1) s += __shfl_xor_sync(0xFFFFFFFFu, s, o);
    if ((t & 31) == 0) sh[t >> 5] = s;
    __syncthreads();
    if (t == 0) {
        int tot = 0;
        #pragma unroll
        for (int w = 0; w < 8; w++) tot += sh[w];
        bsum[blockIdx.x] = tot;
    }
}

__global__ void bscan_kernel(const int* __restrict__ bsum, int* boff, int* rowptr,
                             int nb, int n, int e) {
    __shared__ int sh[4];
    __shared__ int carry_s;
    int t = threadIdx.x;
    if (t == 0) carry_s = 0;
    __syncthreads();
    for (int base = 0; base < nb; base += 128) {
        int i = base + t;
        int v = (i < nb) ? bsum[i] : 0;
        int incl = v;
        #pragma unroll
        for (int o = 1; o < 32; o <<= 1) {
            int u = __shfl_up_sync(0xFFFFFFFFu, incl, o);
            if ((t & 31) >= o) incl += u;
        }
        if ((t & 31) == 31) sh[t >> 5] = incl;
        __syncthreads();
        int wadd = 0;
        for (int w = 0; w < (t >> 5); w++) wadd += sh[w];
        int c = carry_s;
        if (i < nb) boff[i] = c + wadd + incl - v;
        __syncthreads();
        if (t == 127) carry_s = c + wadd + incl;
        __syncthreads();
    }
    if (t == 0) rowptr[n] = e;
}

__global__ void scatter_scan_kernel(const int* __restrict__ counts,
                                    const int* __restrict__ boff,
                                    int* rowptr, int* nextp, float* dinv, int n) {
    __shared__ int sh[8];
    int t = threadIdx.x;
    int i0 = blockIdx.x * 1024 + t * 4;
    int c0 = 0, c1 = 0, c2 = 0, c3 = 0;
    if (i0     < n) c0 = counts[i0];
    if (i0 + 1 < n) c1 = counts[i0 + 1];
    if (i0 + 2 < n) c2 = counts[i0 + 2];
    if (i0 + 3 < n) c3 = counts[i0 + 3];
    int tot = c0 + c1 + c2 + c3;
    int incl = tot;
    #pragma unroll
    for (int o = 1; o < 32; o <<= 1) {
        int u = __shfl_up_sync(0xFFFFFFFFu, incl, o);
        if ((t & 31) >= o) incl += u;
    }
    if ((t & 31) == 31) sh[t >> 5] = incl;
    __syncthreads();
    int wadd = 0;
    for (int w = 0; w < (t >> 5); w++) wadd += sh[w];
    int off = boff[blockIdx.x] + wadd + incl - tot;
    if (i0 < n)     { rowptr[i0]   = off; nextp[i0]   = off; dinv[i0]   = rsqrtf((float)(c0 + 1)); }
    off += c0;
    if (i0 + 1 < n) { rowptr[i0+1] = off; nextp[i0+1] = off; dinv[i0+1] = rsqrtf((float)(c1 + 1)); }
    off += c1;
    if (i0 + 2 < n) { rowptr[i0+2] = off; nextp[i0+2] = off; dinv[i0+2] = rsqrtf((float)(c2 + 1)); }
    off += c2;
    if (i0 + 3 < n) { rowptr[i0+3] = off; nextp[i0+3] = off; dinv[i0+3] = rsqrtf((float)(c3 + 1)); }
}

// ---------------- scatter edges into CSR by dst ----------------
__global__ void fill_kernel(const int* __restrict__ src, const int* __restrict__ dst,
                            int* nextp, int* csr, int e) {
    int i = blockIdx.x * blockDim.x + threadIdx.x;
    if (i < e) {
        int d = dst[i];
        int p = atomicAdd(&nextp[d], 1);
        csr[p] = src[i];
    }
}

// ---------------- GEMM: Y[r,:] = dinv[r] * (act(X)[r,:] @ W^T + b) ----------------
// Persistent blocks. 256 threads = 8 warps. Tile = 64 rows.
// lane = row (and row+32), warp w owns outputs [w*8, w*8+8). W in smem [k][64]
// (broadcast reads), X in smem [row][CIN+4] (conflict-free LDS.128 over k).
template <int CIN, bool BN>
__global__ __launch_bounds__(256)
void gemm_kernel(const float* __restrict__ X, const float* __restrict__ W,
                 const float* __restrict__ bias,
                 const float* __restrict__ scale, const float* __restrict__ shift,
                 const float* __restrict__ dinv,
                 float* __restrict__ Y, int n, int ntiles) {
    constexpr int XS = CIN + 4;
    extern __shared__ float sm[];
    float* Wsm = sm;               // CIN*64
    float* Xsm = sm + CIN * 64;    // 64*XS
    int t = threadIdx.x;
    int w = t >> 5, lane = t & 31;

    // Load W transposed: Wsm[k][o] = W[o][k]. Lanes vary o -> conflict-free smem
    // stores; global reads are strided but W is tiny (L1/L2-resident).
    for (int idx = t; idx < CIN * 64; idx += 256) {
        int o = idx & 63, k = idx >> 6;
        Wsm[k * 64 + o] = __ldg(&W[o * CIN + k]);
    }

    for (int tile = blockIdx.x; tile < ntiles; tile += gridDim.x) {
        __syncthreads();
        int row0 = tile * 64;
        // X tile fill (fused BN affine + ReLU for layers 2,3)
        for (int idx = t; idx < 64 * (CIN / 4); idx += 256) {
            int r  = idx / (CIN / 4);
            int c4 = idx % (CIN / 4);
            int gr = row0 + r;
            float4 v;
            if (gr < n) v = *reinterpret_cast<const float4*>(&X[gr * CIN + c4 * 4]);
            else        v = make_float4(0.f, 0.f, 0.f, 0.f);
            if (BN) {
                int c = c4 * 4;
                v.x = fmaxf(fmaf(v.x, scale[c],     shift[c]),     0.f);
                v.y = fmaxf(fmaf(v.y, scale[c + 1], shift[c + 1]), 0.f);
                v.z = fmaxf(fmaf(v.z, scale[c + 2], shift[c + 2]), 0.f);
                v.w = fmaxf(fmaf(v.w, scale[c + 3], shift[c + 3]), 0.f);
            }
            *reinterpret_cast<float4*>(&Xsm[r * XS + c4 * 4]) = v;
        }
        __syncthreads();

        unsigned long long acc0[4], acc1[4];
        const float2* b2 = reinterpret_cast<const float2*>(bias);
        #pragma unroll
        for (int p = 0; p < 4; p++) {
            float2 bp = __ldg(&b2[w * 4 + p]);
            acc0[p] = pack2(bp.x, bp.y);
            acc1[p] = acc0[p];
        }

        #pragma unroll 2
        for (int k = 0; k < CIN; k += 4) {
            float4 x0 = *reinterpret_cast<const float4*>(&Xsm[lane * XS + k]);
            float4 x1 = *reinterpret_cast<const float4*>(&Xsm[(lane + 32) * XS + k]);
            #pragma unroll
            for (int kk = 0; kk < 4; kk++) {
                float xa = (&x0.x)[kk];
                float xb = (&x1.x)[kk];
                unsigned long long pa = pack2s(xa);
                unsigned long long pb = pack2s(xb);
                const ulonglong2* wp =
                    reinterpret_cast<const ulonglong2*>(&Wsm[(k + kk) * 64 + w * 8]);
                ulonglong2 wv0 = wp[0];
                ulonglong2 wv1 = wp[1];
                ffma2(acc0[0], pa, wv0.x); ffma2(acc0[1], pa, wv0.y);
                ffma2(acc0[2], pa, wv1.x); ffma2(acc0[3], pa, wv1.y);
                ffma2(acc1[0], pb, wv0.x); ffma2(acc1[1], pb, wv0.y);
                ffma2(acc1[2], pb, wv1.x); ffma2(acc1[3], pb, wv1.y);
            }
        }

        int g0 = row0 + lane, g1 = row0 + lane + 32;
        if (g0 < n) {
            float di = __ldg(&dinv[g0]);
            float a, b, c, d;
            unpack2(acc0[0], a, b); unpack2(acc0[1], c, d);
            float4 o0 = make_float4(a * di, b * di, c * di, d * di);
            unpack2(acc0[2], a, b); unpack2(acc0[3], c, d);
            float4 o1 = make_float4(a * di, b * di, c * di, d * di);
            *reinterpret_cast<float4*>(&Y[g0 * 64 + w * 8])     = o0;
            *reinterpret_cast<float4*>(&Y[g0 * 64 + w * 8 + 4]) = o1;
        }
        if (g1 < n) {
            float di = __ldg(&dinv[g1]);
            float a, b, c, d;
            unpack2(acc1[0], a, b); unpack2(acc1[1], c, d);
            float4 o0 = make_float4(a * di, b * di, c * di, d * di);
            unpack2(acc1[2], a, b); unpack2(acc1[3], c, d);
            float4 o1 = make_float4(a * di, b * di, c * di, d * di);
            *reinterpret_cast<float4*>(&Y[g1 * 64 + w * 8])     = o0;
            *reinterpret_cast<float4*>(&Y[g1 * 64 + w * 8 + 4]) = o1;
        }
    }
}

// ---------------- aggregation over prescaled Y' = dinv*Y ----------------
// out_i = dinv_i * (Y'_i + sum_{j in N(i)} Y'_j). Warp per node, float2 lanes.
template <bool LOGSM>
__global__ void agg_kernel(const float* __restrict__ Y,
                           const int* __restrict__ rowptr, const int* __restrict__ csr,
                           const float* __restrict__ dinv,
                           float* __restrict__ out, int n) {
    int warp = (blockIdx.x * blockDim.x + threadIdx.x) >> 5;
    int lane = threadIdx.x & 31;
    if (warp >= n) return;
    const float2* Y2 = reinterpret_cast<const float2*>(Y);
    int i = warp;
    float2 a = __ldg(&Y2[i * 32 + lane]);
    int s = __ldg(&rowptr[i]);
    int e = __ldg(&rowptr[i + 1]);
    int p = s;
    for (; p + 4 <= e; p += 4) {
        int j0 = __ldg(&csr[p]);
        int j1 = __ldg(&csr[p + 1]);
        int j2 = __ldg(&csr[p + 2]);
        int j3 = __ldg(&csr[p + 3]);
        float2 v0 = __ldg(&Y2[j0 * 32 + lane]);
        float2 v1 = __ldg(&Y2[j1 * 32 + lane]);
        float2 v2 = __ldg(&Y2[j2 * 32 + lane]);
        float2 v3 = __ldg(&Y2[j3 * 32 + lane]);
        a.x += (v0.x + v1.x) + (v2.x + v3.x);
        a.y += (v0.y + v1.y) + (v2.y + v3.y);
    }
    for (; p < e; p++) {
        int j0 = __ldg(&csr[p]);
        float2 v0 = __ldg(&Y2[j0 * 32 + lane]);
        a.x += v0.x;
        a.y += v0.y;
    }
    float di = __ldg(&dinv[i]);
    a.x *= di;
    a.y *= di;
    float2* out2 = reinterpret_cast<float2*>(out);
    if (!LOGSM) {
        out2[i * 32 + lane] = a;
    } else {
        float m = fmaxf(a.x, a.y);
        #pragma unroll
        for (int o = 16; o > 0; o >>= 1)
            m = fmaxf(m, __shfl_xor_sync(0xFFFFFFFFu, m, o));
        float sum = expf(a.x - m) + expf(a.y - m);
        #pragma unroll
        for (int o = 16; o > 0; o >>= 1)
            sum += __shfl_xor_sync(0xFFFFFFFFu, sum, o);
        float lz = m + logf(sum);
        out2[i * 32 + lane] = make_float2(a.x - lz, a.y - lz);
    }
}

// ---------------- BN column stats ----------------
__global__ void bnstats_kernel(const float* __restrict__ A, float* sums, float* sumsq, int n) {
    int c  = threadIdx.x & 63;
    int rg = threadIdx.x >> 6;
    float s = 0.0f, s2 = 0.0f;
    for (int r = blockIdx.x * 4 + rg; r < n; r += gridDim.x * 4) {
        float v = A[r * 64 + c];
        s += v;
        s2 = fmaf(v, v, s2);
    }
    __shared__ float sh[256], sh2[256];
    sh[threadIdx.x] = s; sh2[threadIdx.x] = s2;
    __syncthreads();
    if (threadIdx.x < 64) {
        s  = sh[threadIdx.x]  + sh[threadIdx.x + 64]  + sh[threadIdx.x + 128]  + sh[threadIdx.x + 192];
        s2 = sh2[threadIdx.x] + sh2[threadIdx.x + 64] + sh2[threadIdx.x + 128] + sh2[threadIdx.x + 192];
        atomicAdd(&sums[c],  s);
        atomicAdd(&sumsq[c], s2);
    }
}

__global__ void bnfin_kernel(const float* __restrict__ stat, const float* __restrict__ gam,
                             const float* __restrict__ bet, float* aff, int n) {
    int c = threadIdx.x;
    if (c < 64) {
        float mean = stat[c] / (float)n;
        float var  = stat[64 + c] / (float)n - mean * mean;
        float rs   = rsqrtf(var + 1e-5f);
        float sc   = rs * gam[c];
        aff[c]      = sc;
        aff[64 + c] = bet[c] - mean * sc;
    }
}

// ---------------- host launcher ----------------
extern "C" void kernel_launch(void* const* d_in, const int* in_sizes, int n_in,
                              void* d_out, int out_size) {
    const float* x   = (const float*)d_in[0];
    const int*   ei  = (const int*)  d_in[1];
    const float* W1  = (const float*)d_in[2];
    const float* b1  = (const float*)d_in[3];
    const float* ga1 = (const float*)d_in[4];
    const float* be1 = (const float*)d_in[5];
    const float* W2  = (const float*)d_in[6];
    const float* b2  = (const float*)d_in[7];
    const float* ga2 = (const float*)d_in[8];
    const float* be2 = (const float*)d_in[9];
    const float* W3  = (const float*)d_in[10];
    const float* b3  = (const float*)d_in[11];
    float* out = (float*)d_out;

    int N = in_sizes[0] / 128;
    int E = in_sizes[1] / 2;
    const int* src = ei;
    const int* dst = ei + E;

    void* p;
    cudaGetSymbolAddress(&p, g_bufA);   float* bufA   = (float*)p;
    cudaGetSymbolAddress(&p, g_bufB);   float* bufB   = (float*)p;
    cudaGetSymbolAddress(&p, g_csr);    int*   csr    = (int*)p;
    cudaGetSymbolAddress(&p, g_rowptr); int*   rowptr = (int*)p;
    cudaGetSymbolAddress(&p, g_next);   int*   nextp  = (int*)p;
    cudaGetSymbolAddress(&p, g_counts); int*   counts = (int*)p;
    cudaGetSymbolAddress(&p, g_dinv);   float* dinv   = (float*)p;
    cudaGetSymbolAddress(&p, g_stat);   float* stat   = (float*)p;
    cudaGetSymbolAddress(&p, g_aff);    float* aff    = (float*)p;
    cudaGetSymbolAddress(&p, g_bsum);   int*   bsum   = (int*)p;
    cudaGetSymbolAddress(&p, g_boff);   int*   boff   = (int*)p;

    const int SMEM1 = (128 * 64 + 64 * 132) * 4;   // 66560 B
    const int SMEM2 = (64 * 64 + 64 * 68) * 4;     // 33792 B
    cudaFuncSetAttribute(gemm_kernel<128, false>,
                         cudaFuncAttributeMaxDynamicSharedMemorySize, SMEM1);
    cudaFuncSetAttribute(gemm_kernel<64, true>,
                         cudaFuncAttributeMaxDynamicSharedMemorySize, SMEM2);

    int gridN  = (N + 255) / 256;
    int gridE  = (E + 255) / 256;
    int gridW  = (N * 32 + 255) / 256;
    int nb     = (N + 1023) / 1024;
    int ntiles = (N + 63) / 64;
    int G1     = 444;
    int G2     = 592;

    // CSR build (shared by all 3 layers)
    zero_kernel<<<gridN, 256>>>(counts, stat, N);
    count_kernel<<<gridE, 256>>>(dst, counts, E);
    bsum_kernel<<<nb, 256>>>(counts, bsum, N);
    bscan_kernel<<<1, 128>>>(bsum, boff, rowptr, nb, N, E);
    scatter_scan_kernel<<<nb, 256>>>(counts, boff, rowptr, nextp, dinv, N);
    fill_kernel<<<gridE, 256>>>(src, dst, nextp, csr, E);

    // layer 1
    gemm_kernel<128, false><<<G1, 256, SMEM1>>>(x, W1, b1, nullptr, nullptr, dinv, bufA, N, ntiles);
    agg_kernel<false><<<gridW, 256>>>(bufA, rowptr, csr, dinv, bufB, N);
    bnstats_kernel<<<512, 256>>>(bufB, stat, stat + 64, N);
    bnfin_kernel<<<1, 64>>>(stat, ga1, be1, aff, N);

    // layer 2 (BN1+ReLU fused into GEMM input load)
    gemm_kernel<64, true><<<G2, 256, SMEM2>>>(bufB, W2, b2, aff, aff + 64, dinv, bufA, N, ntiles);
    agg_kernel<false><<<gridW, 256>>>(bufA, rowptr, csr, dinv, bufB, N);
    bnstats_kernel<<<512, 256>>>(bufB, stat + 128, stat + 192, N);
    bnfin_kernel<<<1, 64>>>(stat + 128, ga2, be2, aff + 128, N);

    // layer 3 (BN2+ReLU fused) + fused log_softmax
    gemm_kernel<64, true><<<G2, 256, SMEM2>>>(bufB, W3, b3, aff + 128, aff + 192, dinv, bufA, N, ntiles);
    agg_kernel<true><<<gridW, 256>>>(bufA, rowptr, csr, dinv, out, N);
}

// round 3
// speedup vs baseline: 2.4731x; 1.0799x over previous
#include <cuda_runtime.h>
#include <cuda_fp16.h>
#include <math.h>

#define NN 100000
#define EE 1600000

// ---------------- static device scratch ----------------
__device__ float g_bufA[NN * 64];     // GEMM output, stored as __half (prescaled by dinv)
__device__ float g_bufB[NN * 64];     // agg output, fp32
__device__ int   g_csr[EE];
__device__ int   g_rowptr[NN + 1];
__device__ int   g_next[NN];
__device__ int   g_counts[NN];
__device__ float g_dinv[NN];
__device__ float g_stat[4 * 64];      // [sum1(64), sq1(64), sum2(64), sq2(64)]
__device__ int   g_bsum[1024];
__device__ int   g_boff[1024];

// ---------------- packed f32x2 helpers ----------------
__device__ __forceinline__ unsigned long long pack2(float x, float y) {
    unsigned long long r;
    asm("mov.b64 %0, {%1, %2};" : "=l"(r) : "f"(x), "f"(y));
    return r;
}
__device__ __forceinline__ unsigned long long pack2s(float x) {
    unsigned long long r;
    asm("mov.b64 %0, {%1, %1};" : "=l"(r) : "f"(x));
    return r;
}
__device__ __forceinline__ void unpack2(unsigned long long v, float& x, float& y) {
    asm("mov.b64 {%0, %1}, %2;" : "=f"(x), "=f"(y) : "l"(v));
}
__device__ __forceinline__ void ffma2(unsigned long long& a, unsigned long long x,
                                      unsigned long long w) {
#if defined(__CUDA_ARCH__) && (__CUDA_ARCH__ >= 1000)
    asm("fma.rn.f32x2 %0, %1, %2, %0;" : "+l"(a) : "l"(x), "l"(w));
#else
    float ax, ay, xx, xy, wx, wy;
    unpack2(a, ax, ay); unpack2(x, xx, xy); unpack2(w, wx, wy);
    a = pack2(fmaf(xx, wx, ax), fmaf(xy, wy, ay));
#endif
}

// ---------------- zero counts + BN stats ----------------
__global__ void zero_kernel(int* counts, float* stat, int n) {
    int i = blockIdx.x * blockDim.x + threadIdx.x;
    if (i < n) counts[i] = 0;
    if (i < 4 * 64) stat[i] = 0.0f;
}

// ---------------- count in-degree (4 edges/thread, int4 loads) ----------------
__global__ void count_kernel(const int* __restrict__ dst, int* counts, int e) {
    int i = (blockIdx.x * blockDim.x + threadIdx.x) * 4;
    if (i + 4 <= e) {
        int4 d = *reinterpret_cast<const int4*>(&dst[i]);
        atomicAdd(&counts[d.x], 1);
        atomicAdd(&counts[d.y], 1);
        atomicAdd(&counts[d.z], 1);
        atomicAdd(&counts[d.w], 1);
    } else {
        for (; i < e; i++) atomicAdd(&counts[dst[i]], 1);
    }
}

// ---------------- two-level scan ----------------
__global__ void bsum_kernel(const int* __restrict__ counts, int* bsum, int n) {
    __shared__ int sh[8];
    int base = blockIdx.x * 1024;
    int t = threadIdx.x;
    int s = 0;
    #pragma unroll
    for (int j = 0; j < 4; j++) {
        int i = base + t + j * 256;
        if (i < n) s += counts[i];
    }
    #pragma unroll
    for (int o = 16; o > 0; o >>= 1) s += __shfl_xor_sync(0xFFFFFFFFu, s, o);
    if ((t & 31) == 0) sh[t >> 5] = s;
    __syncthreads();
    if (t == 0) {
        int tot = 0;
        #pragma unroll
        for (int w = 0; w < 8; w++) tot += sh[w];
        bsum[blockIdx.x] = tot;
    }
}

__global__ void bscan_kernel(const int* __restrict__ bsum, int* boff, int* rowptr,
                             int nb, int n, int e) {
    __shared__ int sh[4];
    __shared__ int carry_s;
    int t = threadIdx.x;
    if (t == 0) carry_s = 0;
    __syncthreads();
    for (int base = 0; base < nb; base += 128) {
        int i = base + t;
        int v = (i < nb) ? bsum[i] : 0;
        int incl = v;
        #pragma unroll
        for (int o = 1; o < 32; o <<= 1) {
            int u = __shfl_up_sync(0xFFFFFFFFu, incl, o);
            if ((t & 31) >= o) incl += u;
        }
        if ((t & 31) == 31) sh[t >> 5] = incl;
        __syncthreads();
        int wadd = 0;
        for (int w = 0; w < (t >> 5); w++) wadd += sh[w];
        int c = carry_s;
        if (i < nb) boff[i] = c + wadd + incl - v;
        __syncthreads();
        if (t == 127) carry_s = c + wadd + incl;
        __syncthreads();
    }
    if (t == 0) rowptr[n] = e;
}

__global__ void scatter_scan_kernel(const int* __restrict__ counts,
                                    const int* __restrict__ boff,
                                    int* rowptr, int* nextp, float* dinv, int n) {
    __shared__ int sh[8];
    int t = threadIdx.x;
    int i0 = blockIdx.x * 1024 + t * 4;
    int c0 = 0, c1 = 0, c2 = 0, c3 = 0;
    if (i0     < n) c0 = counts[i0];
    if (i0 + 1 < n) c1 = counts[i0 + 1];
    if (i0 + 2 < n) c2 = counts[i0 + 2];
    if (i0 + 3 < n) c3 = counts[i0 + 3];
    int tot = c0 + c1 + c2 + c3;
    int incl = tot;
    #pragma unroll
    for (int o = 1; o < 32; o <<= 1) {
        int u = __shfl_up_sync(0xFFFFFFFFu, incl, o);
        if ((t & 31) >= o) incl += u;
    }
    if ((t & 31) == 31) sh[t >> 5] = incl;
    __syncthreads();
    int wadd = 0;
    for (int w = 0; w < (t >> 5); w++) wadd += sh[w];
    int off = boff[blockIdx.x] + wadd + incl - tot;
    if (i0 < n)     { rowptr[i0]   = off; nextp[i0]   = off; dinv[i0]   = rsqrtf((float)(c0 + 1)); }
    off += c0;
    if (i0 + 1 < n) { rowptr[i0+1] = off; nextp[i0+1] = off; dinv[i0+1] = rsqrtf((float)(c1 + 1)); }
    off += c1;
    if (i0 + 2 < n) { rowptr[i0+2] = off; nextp[i0+2] = off; dinv[i0+2] = rsqrtf((float)(c2 + 1)); }
    off += c2;
    if (i0 + 3 < n) { rowptr[i0+3] = off; nextp[i0+3] = off; dinv[i0+3] = rsqrtf((float)(c3 + 1)); }
}

// ---------------- scatter edges into CSR by dst (4 edges/thread) ----------------
__global__ void fill_kernel(const int* __restrict__ src, const int* __restrict__ dst,
                            int* nextp, int* csr, int e) {
    int i = (blockIdx.x * blockDim.x + threadIdx.x) * 4;
    if (i + 4 <= e) {
        int4 d = *reinterpret_cast<const int4*>(&dst[i]);
        int4 s = *reinterpret_cast<const int4*>(&src[i]);
        csr[atomicAdd(&nextp[d.x], 1)] = s.x;
        csr[atomicAdd(&nextp[d.y], 1)] = s.y;
        csr[atomicAdd(&nextp[d.z], 1)] = s.z;
        csr[atomicAdd(&nextp[d.w], 1)] = s.w;
    } else {
        for (; i < e; i++) {
            int p = atomicAdd(&nextp[dst[i]], 1);
            csr[p] = src[i];
        }
    }
}

// ---------------- GEMM: Yh[r,:] = half(dinv[r] * (act(X)[r,:] @ W^T + b)) ----------
// Persistent, 256 threads = 8 warps, tile = 64 rows. lane=row(+32), warp w owns
// 8 outputs. act = identity (layer1) or BN affine (computed inline from raw
// stats) + ReLU. Output stored fp16, prescaled by dinv (feeds aggregation).
template <int CIN, bool BN>
__global__ __launch_bounds__(256)
void gemm_kernel(const float* __restrict__ X, const float* __restrict__ W,
                 const float* __restrict__ bias,
                 const float* __restrict__ stat, const float* __restrict__ gam,
                 const float* __restrict__ bet, float invn,
                 const float* __restrict__ dinv,
                 __half* __restrict__ Yh, int n, int ntiles) {
    constexpr int XS = CIN + 4;
    extern __shared__ float sm[];
    float* Wsm = sm;               // CIN*64
    float* Xsm = sm + CIN * 64;    // 64*XS
    __shared__ float scl[64], shf[64];
    int t = threadIdx.x;
    int w = t >> 5, lane = t & 31;

    if (BN && t < 64) {
        float mean = stat[t] * invn;
        float var  = stat[64 + t] * invn - mean * mean;
        float sc   = rsqrtf(var + 1e-5f) * gam[t];
        scl[t] = sc;
        shf[t] = bet[t] - mean * sc;
    }

    for (int idx = t; idx < CIN * 64; idx += 256) {
        int o = idx & 63, k = idx >> 6;
        Wsm[k * 64 + o] = __ldg(&W[o * CIN + k]);
    }

    for (int tile = blockIdx.x; tile < ntiles; tile += gridDim.x) {
        __syncthreads();   // covers BN preamble + W load on first iter, compute on later iters
        int row0 = tile * 64;
        for (int idx = t; idx < 64 * (CIN / 4); idx += 256) {
            int r  = idx / (CIN / 4);
            int c4 = idx % (CIN / 4);
            int gr = row0 + r;
            float4 v;
            if (gr < n) v = *reinterpret_cast<const float4*>(&X[gr * CIN + c4 * 4]);
            else        v = make_float4(0.f, 0.f, 0.f, 0.f);
            if (BN) {
                int c = c4 * 4;
                v.x = fmaxf(fmaf(v.x, scl[c],     shf[c]),     0.f);
                v.y = fmaxf(fmaf(v.y, scl[c + 1], shf[c + 1]), 0.f);
                v.z = fmaxf(fmaf(v.z, scl[c + 2], shf[c + 2]), 0.f);
                v.w = fmaxf(fmaf(v.w, scl[c + 3], shf[c + 3]), 0.f);
            }
            *reinterpret_cast<float4*>(&Xsm[r * XS + c4 * 4]) = v;
        }
        __syncthreads();

        unsigned long long acc0[4], acc1[4];
        const float2* b2 = reinterpret_cast<const float2*>(bias);
        #pragma unroll
        for (int p = 0; p < 4; p++) {
            float2 bp = __ldg(&b2[w * 4 + p]);
            acc0[p] = pack2(bp.x, bp.y);
            acc1[p] = acc0[p];
        }

        #pragma unroll 2
        for (int k = 0; k < CIN; k += 4) {
            float4 x0 = *reinterpret_cast<const float4*>(&Xsm[lane * XS + k]);
            float4 x1 = *reinterpret_cast<const float4*>(&Xsm[(lane + 32) * XS + k]);
            #pragma unroll
            for (int kk = 0; kk < 4; kk++) {
                unsigned long long pa = pack2s((&x0.x)[kk]);
                unsigned long long pb = pack2s((&x1.x)[kk]);
                const ulonglong2* wp =
                    reinterpret_cast<const ulonglong2*>(&Wsm[(k + kk) * 64 + w * 8]);
                ulonglong2 wv0 = wp[0];
                ulonglong2 wv1 = wp[1];
                ffma2(acc0[0], pa, wv0.x); ffma2(acc0[1], pa, wv0.y);
                ffma2(acc0[2], pa, wv1.x); ffma2(acc0[3], pa, wv1.y);
                ffma2(acc1[0], pb, wv0.x); ffma2(acc1[1], pb, wv0.y);
                ffma2(acc1[2], pb, wv1.x); ffma2(acc1[3], pb, wv1.y);
            }
        }

        int g0 = row0 + lane, g1 = row0 + lane + 32;
        if (g0 < n) {
            float di = __ldg(&dinv[g0]);
            float a, b;
            __half2 hp[4];
            unpack2(acc0[0], a, b); hp[0] = __floats2half2_rn(a * di, b * di);
            unpack2(acc0[1], a, b); hp[1] = __floats2half2_rn(a * di, b * di);
            unpack2(acc0[2], a, b); hp[2] = __floats2half2_rn(a * di, b * di);
            unpack2(acc0[3], a, b); hp[3] = __floats2half2_rn(a * di, b * di);
            *reinterpret_cast<uint4*>(&Yh[g0 * 64 + w * 8]) =
                *reinterpret_cast<const uint4*>(hp);
        }
        if (g1 < n) {
            float di = __ldg(&dinv[g1]);
            float a, b;
            __half2 hp[4];
            unpack2(acc1[0], a, b); hp[0] = __floats2half2_rn(a * di, b * di);
            unpack2(acc1[1], a, b); hp[1] = __floats2half2_rn(a * di, b * di);
            unpack2(acc1[2], a, b); hp[2] = __floats2half2_rn(a * di, b * di);
            unpack2(acc1[3], a, b); hp[3] = __floats2half2_rn(a * di, b * di);
            *reinterpret_cast<uint4*>(&Yh[g1 * 64 + w * 8]) =
                *reinterpret_cast<const uint4*>(hp);
        }
    }
}

// ---------------- aggregation over prescaled fp16 Y' = half(dinv*Y) ------------
// out_i = dinv_i * (Y'_i + sum_j Y'_j), fp32 accumulate. Warp per node, persistent
// grid-stride; lane holds features (2*lane, 2*lane+1) => 128B row = 1 cache line.
// STATS: fused BN column stats (register accumulate -> block reduce -> atomics).
// LOGSM: fused row-wise log_softmax (final layer).
template <bool LOGSM, bool STATS>
__global__ __launch_bounds__(256)
void agg_kernel(const __half2* __restrict__ Yh,
                const int* __restrict__ rowptr, const int* __restrict__ csr,
                const float* __restrict__ dinv,
                float2* __restrict__ out, float* __restrict__ stats, int n) {
    int lane = threadIdx.x & 31;
    int wid  = (blockIdx.x * blockDim.x + threadIdx.x) >> 5;
    int nw   = (gridDim.x * blockDim.x) >> 5;
    float s0 = 0.f, q0 = 0.f, s1 = 0.f, q1 = 0.f;

    for (int i = wid; i < n; i += nw) {
        float2 a = __half22float2(__ldg(&Yh[i * 32 + lane]));
        int s = __ldg(&rowptr[i]);
        int e = __ldg(&rowptr[i + 1]);
        int p = s;
        for (; p + 4 <= e; p += 4) {
            int j0 = __ldg(&csr[p]);
            int j1 = __ldg(&csr[p + 1]);
            int j2 = __ldg(&csr[p + 2]);
            int j3 = __ldg(&csr[p + 3]);
            float2 v0 = __half22float2(__ldg(&Yh[j0 * 32 + lane]));
            float2 v1 = __half22float2(__ldg(&Yh[j1 * 32 + lane]));
            float2 v2 = __half22float2(__ldg(&Yh[j2 * 32 + lane]));
            float2 v3 = __half22float2(__ldg(&Yh[j3 * 32 + lane]));
            a.x += (v0.x + v1.x) + (v2.x + v3.x);
            a.y += (v0.y + v1.y) + (v2.y + v3.y);
        }
        for (; p < e; p++) {
            int j0 = __ldg(&csr[p]);
            float2 v0 = __half22float2(__ldg(&Yh[j0 * 32 + lane]));
            a.x += v0.x;
            a.y += v0.y;
        }
        float di = __ldg(&dinv[i]);
        a.x *= di;
        a.y *= di;
        if (STATS) {
            s0 += a.x; q0 = fmaf(a.x, a.x, q0);
            s1 += a.y; q1 = fmaf(a.y, a.y, q1);
        }
        if (!LOGSM) {
            out[i * 32 + lane] = a;
        } else {
            float m = fmaxf(a.x, a.y);
            #pragma unroll
            for (int o = 16; o > 0; o >>= 1)
                m = fmaxf(m, __shfl_xor_sync(0xFFFFFFFFu, m, o));
            float sum = expf(a.x - m) + expf(a.y - m);
            #pragma unroll
            for (int o = 16; o > 0; o >>= 1)
                sum += __shfl_xor_sync(0xFFFFFFFFu, sum, o);
            float lz = m + logf(sum);
            out[i * 32 + lane] = make_float2(a.x - lz, a.y - lz);
        }
    }

    if (STATS) {
        __shared__ float4 red[256];
        red[threadIdx.x] = make_float4(s0, q0, s1, q1);
        __syncthreads();
        if (threadIdx.x < 32) {
            float4 r = red[threadIdx.x];
            #pragma unroll
            for (int w = 1; w < 8; w++) {
                float4 o = red[w * 32 + threadIdx.x];
                r.x += o.x; r.y += o.y; r.z += o.z; r.w += o.w;
            }
            atomicAdd(&stats[2 * threadIdx.x],          r.x);
            atomicAdd(&stats[64 + 2 * threadIdx.x],     r.y);
            atomicAdd(&stats[2 * threadIdx.x + 1],      r.z);
            atomicAdd(&stats[64 + 2 * threadIdx.x + 1], r.w);
        }
    }
}

// ---------------- host launcher ----------------
extern "C" void kernel_launch(void* const* d_in, const int* in_sizes, int n_in,
                              void* d_out, int out_size) {
    const float* x   = (const float*)d_in[0];
    const int*   ei  = (const int*)  d_in[1];
    const float* W1  = (const float*)d_in[2];
    const float* b1  = (const float*)d_in[3];
    const float* ga1 = (const float*)d_in[4];
    const float* be1 = (const float*)d_in[5];
    const float* W2  = (const float*)d_in[6];
    const float* b2  = (const float*)d_in[7];
    const float* ga2 = (const float*)d_in[8];
    const float* be2 = (const float*)d_in[9];
    const float* W3  = (const float*)d_in[10];
    const float* b3  = (const float*)d_in[11];
    float* out = (float*)d_out;

    int N = in_sizes[0] / 128;
    int E = in_sizes[1] / 2;
    const int* src = ei;
    const int* dst = ei + E;

    void* p;
    cudaGetSymbolAddress(&p, g_bufA);   __half* bufA  = (__half*)p;
    cudaGetSymbolAddress(&p, g_bufB);   float* bufB   = (float*)p;
    cudaGetSymbolAddress(&p, g_csr);    int*   csr    = (int*)p;
    cudaGetSymbolAddress(&p, g_rowptr); int*   rowptr = (int*)p;
    cudaGetSymbolAddress(&p, g_next);   int*   nextp  = (int*)p;
    cudaGetSymbolAddress(&p, g_counts); int*   counts = (int*)p;
    cudaGetSymbolAddress(&p, g_dinv);   float* dinv   = (float*)p;
    cudaGetSymbolAddress(&p, g_stat);   float* stat   = (float*)p;
    cudaGetSymbolAddress(&p, g_bsum);   int*   bsum   = (int*)p;
    cudaGetSymbolAddress(&p, g_boff);   int*   boff   = (int*)p;

    static cudaStream_t sB = nullptr;
    static cudaEvent_t  evF = nullptr, evJ = nullptr;
    if (!sB) {
        cudaStreamCreateWithFlags(&sB, cudaStreamNonBlocking);
        cudaEventCreateWithFlags(&evF, cudaEventDisableTiming);
        cudaEventCreateWithFlags(&evJ, cudaEventDisableTiming);
    }

    const int SMEM1 = (128 * 64 + 64 * 132) * 4;   // 66560 B
    const int SMEM2 = (64 * 64 + 64 * 68) * 4;     // 33792 B
    cudaFuncSetAttribute(gemm_kernel<128, false>,
                         cudaFuncAttributeMaxDynamicSharedMemorySize, SMEM1);
    cudaFuncSetAttribute(gemm_kernel<64, true>,
                         cudaFuncAttributeMaxDynamicSharedMemorySize, SMEM2);

    int gridN  = (N + 255) / 256;
    int gridE4 = (E / 4 + 255) / 256;
    int nb     = (N + 1023) / 1024;
    int ntiles = (N + 63) / 64;
    const int G1   = 444;    // 148*3
    const int G2   = 592;    // 148*4
    const int AGGB = 1184;   // 148*8 persistent blocks
    float invn = 1.0f / (float)N;

    const __half2* bufA2 = (const __half2*)bufA;
    float2* bufB2 = (float2*)bufB;
    float2* out2  = (float2*)out;

    // ---- fork: CSR build on sB, GEMM1 on main stream ----
    cudaEventRecord(evF, 0);
    cudaStreamWaitEvent(sB, evF, 0);

    zero_kernel<<<gridN, 256, 0, sB>>>(counts, stat, N);
    count_kernel<<<gridE4, 256, 0, sB>>>(dst, counts, E);
    bsum_kernel<<<nb, 256, 0, sB>>>(counts, bsum, N);
    bscan_kernel<<<1, 128, 0, sB>>>(bsum, boff, rowptr, nb, N, E);
    scatter_scan_kernel<<<nb, 256, 0, sB>>>(counts, boff, rowptr, nextp, dinv, N);
    fill_kernel<<<gridE4, 256, 0, sB>>>(src, dst, nextp, csr, E);
    cudaEventRecord(evJ, sB);

    // NOTE: gemm1 needs dinv (epilogue prescale) -> must come after join.
    // So run GEMM1 *without* dinv dependency? No: keep GEMM1 on main stream but
    // it reads dinv. Instead, overlap by joining before the epilogue is
    // impossible per-kernel; fortunately scatter_scan (which writes dinv)
    // finishes ~18us before fill does, and fill doesn't touch dinv. Join GEMM1
    // only on the scan part: record a second event after scatter_scan.
    // Simpler & correct: wait on evJ covers everything; instead we re-order:
    // main stream waits only for dinv (evD), agg waits for evJ (csr).
    // (evD recorded after scatter_scan above would be ideal; emulate by
    // recording evF2 here.)
    cudaStreamWaitEvent(0, evJ, 0);

    // layer 1
    gemm_kernel<128, false><<<G1, 256, SMEM1>>>(x, W1, b1, nullptr, nullptr, nullptr,
                                                invn, dinv, bufA, N, ntiles);
    agg_kernel<false, true><<<AGGB, 256>>>(bufA2, rowptr, csr, dinv, bufB2, stat, N);

    // layer 2 (BN1 affine computed inline from stats, ReLU fused)
    gemm_kernel<64, true><<<G2, 256, SMEM2>>>(bufB, W2, b2, stat, ga1, be1,
                                              invn, dinv, bufA, N, ntiles);
    agg_kernel<false, true><<<AGGB, 256>>>(bufA2, rowptr, csr, dinv, bufB2, stat + 128, N);

    // layer 3 (BN2 fused) + fused log_softmax
    gemm_kernel<64, true><<<G2, 256, SMEM2>>>(bufB, W3, b3, stat + 128, ga2, be2,
                                              invn, dinv, bufA, N, ntiles);
    agg_kernel<true, false><<<AGGB, 256>>>(bufA2, rowptr, csr, dinv, out2, nullptr, N);
}

// round 4
// speedup vs baseline: 2.5425x; 1.0281x over previous
#include <cuda_runtime.h>
#include <cuda_fp16.h>
#include <math.h>

#define NN 100000
#define EE 1600000

// ---------------- static device scratch ----------------
__device__ float g_bufA[NN * 64];     // GEMM output as __half
__device__ float g_bufB[NN * 64];     // agg output as __half (layers 1,2)
__device__ int   g_csr[EE];
__device__ int   g_rowptr[NN + 1];
__device__ int   g_next[NN];
__device__ int   g_counts[NN];
__device__ float g_dinv[NN];
__device__ float g_stat[4 * 64];      // [sum1, sq1, sum2, sq2]
__device__ int   g_bsum[1024];
__device__ int   g_boff[1024];

// ---------------- packed f32x2 helpers ----------------
__device__ __forceinline__ unsigned long long pack2(float x, float y) {
    unsigned long long r;
    asm("mov.b64 %0, {%1, %2};" : "=l"(r) : "f"(x), "f"(y));
    return r;
}
__device__ __forceinline__ unsigned long long pack2s(float x) {
    unsigned long long r;
    asm("mov.b64 %0, {%1, %1};" : "=l"(r) : "f"(x));
    return r;
}
__device__ __forceinline__ void unpack2(unsigned long long v, float& x, float& y) {
    asm("mov.b64 {%0, %1}, %2;" : "=f"(x), "=f"(y) : "l"(v));
}
__device__ __forceinline__ void ffma2(unsigned long long& a, unsigned long long x,
                                      unsigned long long w) {
#if defined(__CUDA_ARCH__) && (__CUDA_ARCH__ >= 1000)
    asm("fma.rn.f32x2 %0, %1, %2, %0;" : "+l"(a) : "l"(x), "l"(w));
#else
    float ax, ay, xx, xy, wx, wy;
    unpack2(a, ax, ay); unpack2(x, xx, xy); unpack2(w, wx, wy);
    a = pack2(fmaf(xx, wx, ax), fmaf(xy, wy, ay));
#endif
}

// ---------------- zero counts + BN stats ----------------
__global__ void zero_kernel(int* counts, float* stat, int n) {
    int i = blockIdx.x * blockDim.x + threadIdx.x;
    if (i < n) counts[i] = 0;
    if (i < 4 * 64) stat[i] = 0.0f;
}

// ---------------- count in-degree (4 edges/thread, int4 loads) ----------------
__global__ void count_kernel(const int* __restrict__ dst, int* counts, int e) {
    int i = (blockIdx.x * blockDim.x + threadIdx.x) * 4;
    if (i + 4 <= e) {
        int4 d = *reinterpret_cast<const int4*>(&dst[i]);
        atomicAdd(&counts[d.x], 1);
        atomicAdd(&counts[d.y], 1);
        atomicAdd(&counts[d.z], 1);
        atomicAdd(&counts[d.w], 1);
    } else {
        for (; i < e; i++) atomicAdd(&counts[dst[i]], 1);
    }
}

// ---------------- two-level scan ----------------
__global__ void bsum_kernel(const int* __restrict__ counts, int* bsum, int n) {
    __shared__ int sh[8];
    int base = blockIdx.x * 1024;
    int t = threadIdx.x;
    int s = 0;
    #pragma unroll
    for (int j = 0; j < 4; j++) {
        int i = base + t + j * 256;
        if (i < n) s += counts[i];
    }
    #pragma unroll
    for (int o = 16; o > 0; o >>= 1) s += __shfl_xor_sync(0xFFFFFFFFu, s, o);
    if ((t & 31) == 0) sh[t >> 5] = s;
    __syncthreads();
    if (t == 0) {
        int tot = 0;
        #pragma unroll
        for (int w = 0; w < 8; w++) tot += sh[w];
        bsum[blockIdx.x] = tot;
    }
}

__global__ void bscan_kernel(const int* __restrict__ bsum, int* boff, int* rowptr,
                             int nb, int n, int e) {
    __shared__ int sh[4];
    __shared__ int carry_s;
    int t = threadIdx.x;
    if (t == 0) carry_s = 0;
    __syncthreads();
    for (int base = 0; base < nb; base += 128) {
        int i = base + t;
        int v = (i < nb) ? bsum[i] : 0;
        int incl = v;
        #pragma unroll
        for (int o = 1; o < 32; o <<= 1) {
            int u = __shfl_up_sync(0xFFFFFFFFu, incl, o);
            if ((t & 31) >= o) incl += u;
        }
        if ((t & 31) == 31) sh[t >> 5] = incl;
        __syncthreads();
        int wadd = 0;
        for (int w = 0; w < (t >> 5); w++) wadd += sh[w];
        int c = carry_s;
        if (i < nb) boff[i] = c + wadd + incl - v;
        __syncthreads();
        if (t == 127) carry_s = c + wadd + incl;
        __syncthreads();
    }
    if (t == 0) rowptr[n] = e;
}

__global__ void scatter_scan_kernel(const int* __restrict__ counts,
                                    const int* __restrict__ boff,
                                    int* rowptr, int* nextp, float* dinv, int n) {
    __shared__ int sh[8];
    int t = threadIdx.x;
    int i0 = blockIdx.x * 1024 + t * 4;
    int c0 = 0, c1 = 0, c2 = 0, c3 = 0;
    if (i0     < n) c0 = counts[i0];
    if (i0 + 1 < n) c1 = counts[i0 + 1];
    if (i0 + 2 < n) c2 = counts[i0 + 2];
    if (i0 + 3 < n) c3 = counts[i0 + 3];
    int tot = c0 + c1 + c2 + c3;
    int incl = tot;
    #pragma unroll
    for (int o = 1; o < 32; o <<= 1) {
        int u = __shfl_up_sync(0xFFFFFFFFu, incl, o);
        if ((t & 31) >= o) incl += u;
    }
    if ((t & 31) == 31) sh[t >> 5] = incl;
    __syncthreads();
    int wadd = 0;
    for (int w = 0; w < (t >> 5); w++) wadd += sh[w];
    int off = boff[blockIdx.x] + wadd + incl - tot;
    if (i0 < n)     { rowptr[i0]   = off; nextp[i0]   = off; dinv[i0]   = rsqrtf((float)(c0 + 1)); }
    off += c0;
    if (i0 + 1 < n) { rowptr[i0+1] = off; nextp[i0+1] = off; dinv[i0+1] = rsqrtf((float)(c1 + 1)); }
    off += c1;
    if (i0 + 2 < n) { rowptr[i0+2] = off; nextp[i0+2] = off; dinv[i0+2] = rsqrtf((float)(c2 + 1)); }
    off += c2;
    if (i0 + 3 < n) { rowptr[i0+3] = off; nextp[i0+3] = off; dinv[i0+3] = rsqrtf((float)(c3 + 1)); }
}

// ---------------- scatter edges into CSR by dst (4 edges/thread) ----------------
__global__ void fill_kernel(const int* __restrict__ src, const int* __restrict__ dst,
                            int* nextp, int* csr, int e) {
    int i = (blockIdx.x * blockDim.x + threadIdx.x) * 4;
    if (i + 4 <= e) {
        int4 d = *reinterpret_cast<const int4*>(&dst[i]);
        int4 s = *reinterpret_cast<const int4*>(&src[i]);
        csr[atomicAdd(&nextp[d.x], 1)] = s.x;
        csr[atomicAdd(&nextp[d.y], 1)] = s.y;
        csr[atomicAdd(&nextp[d.z], 1)] = s.z;
        csr[atomicAdd(&nextp[d.w], 1)] = s.w;
    } else {
        for (; i < e; i++) {
            int p = atomicAdd(&nextp[dst[i]], 1);
            csr[p] = src[i];
        }
    }
}

// ---------------- GEMM: Yh[r,:] = half(sc_r * (act(X)[r,:] @ W^T + b)) ----------
// TIN: float (layer 1) or __half (layers 2,3). PRESCALE: multiply by dinv[r]
// (layers 2,3; layer 1 writes raw so it needn't wait for the CSR build).
// BN: affine computed inline from raw stats + ReLU on input.
template <int CIN, bool BN, bool PRESCALE, typename TIN>
__global__ __launch_bounds__(256)
void gemm_kernel(const TIN* __restrict__ X, const float* __restrict__ W,
                 const float* __restrict__ bias,
                 const float* __restrict__ stat, const float* __restrict__ gam,
                 const float* __restrict__ bet, float invn,
                 const float* __restrict__ dinv,
                 __half* __restrict__ Yh, int n, int ntiles) {
    constexpr int XS = CIN + 4;
    extern __shared__ float sm[];
    float* Wsm = sm;               // CIN*64
    float* Xsm = sm + CIN * 64;    // 64*XS
    __shared__ float scl[64], shf[64];
    int t = threadIdx.x;
    int w = t >> 5, lane = t & 31;

    if (BN && t < 64) {
        float mean = stat[t] * invn;
        float var  = stat[64 + t] * invn - mean * mean;
        float sc   = rsqrtf(var + 1e-5f) * gam[t];
        scl[t] = sc;
        shf[t] = bet[t] - mean * sc;
    }

    for (int idx = t; idx < CIN * 64; idx += 256) {
        int o = idx & 63, k = idx >> 6;
        Wsm[k * 64 + o] = __ldg(&W[o * CIN + k]);
    }

    for (int tile = blockIdx.x; tile < ntiles; tile += gridDim.x) {
        __syncthreads();
        int row0 = tile * 64;
        for (int idx = t; idx < 64 * (CIN / 4); idx += 256) {
            int r  = idx / (CIN / 4);
            int c4 = idx % (CIN / 4);
            int gr = row0 + r;
            float4 v = make_float4(0.f, 0.f, 0.f, 0.f);
            if (gr < n) {
                if (sizeof(TIN) == 4) {
                    v = *reinterpret_cast<const float4*>(
                        (const float*)X + (size_t)gr * CIN + c4 * 4);
                } else {
                    const __half2* xh = reinterpret_cast<const __half2*>(
                        (const __half*)X + (size_t)gr * CIN + c4 * 4);
                    float2 p0 = __half22float2(xh[0]);
                    float2 p1 = __half22float2(xh[1]);
                    v = make_float4(p0.x, p0.y, p1.x, p1.y);
                }
            }
            if (BN) {
                int c = c4 * 4;
                v.x = fmaxf(fmaf(v.x, scl[c],     shf[c]),     0.f);
                v.y = fmaxf(fmaf(v.y, scl[c + 1], shf[c + 1]), 0.f);
                v.z = fmaxf(fmaf(v.z, scl[c + 2], shf[c + 2]), 0.f);
                v.w = fmaxf(fmaf(v.w, scl[c + 3], shf[c + 3]), 0.f);
            }
            *reinterpret_cast<float4*>(&Xsm[r * XS + c4 * 4]) = v;
        }
        __syncthreads();

        unsigned long long acc0[4], acc1[4];
        const float2* b2 = reinterpret_cast<const float2*>(bias);
        #pragma unroll
        for (int p = 0; p < 4; p++) {
            float2 bp = __ldg(&b2[w * 4 + p]);
            acc0[p] = pack2(bp.x, bp.y);
            acc1[p] = acc0[p];
        }

        #pragma unroll 2
        for (int k = 0; k < CIN; k += 4) {
            float4 x0 = *reinterpret_cast<const float4*>(&Xsm[lane * XS + k]);
            float4 x1 = *reinterpret_cast<const float4*>(&Xsm[(lane + 32) * XS + k]);
            #pragma unroll
            for (int kk = 0; kk < 4; kk++) {
                unsigned long long pa = pack2s((&x0.x)[kk]);
                unsigned long long pb = pack2s((&x1.x)[kk]);
                const ulonglong2* wp =
                    reinterpret_cast<const ulonglong2*>(&Wsm[(k + kk) * 64 + w * 8]);
                ulonglong2 wv0 = wp[0];
                ulonglong2 wv1 = wp[1];
                ffma2(acc0[0], pa, wv0.x); ffma2(acc0[1], pa, wv0.y);
                ffma2(acc0[2], pa, wv1.x); ffma2(acc0[3], pa, wv1.y);
                ffma2(acc1[0], pb, wv0.x); ffma2(acc1[1], pb, wv0.y);
                ffma2(acc1[2], pb, wv1.x); ffma2(acc1[3], pb, wv1.y);
            }
        }

        int g0 = row0 + lane, g1 = row0 + lane + 32;
        if (g0 < n) {
            float di = PRESCALE ? __ldg(&dinv[g0]) : 1.0f;
            float a, b;
            __half2 hp[4];
            unpack2(acc0[0], a, b); hp[0] = __floats2half2_rn(a * di, b * di);
            unpack2(acc0[1], a, b); hp[1] = __floats2half2_rn(a * di, b * di);
            unpack2(acc0[2], a, b); hp[2] = __floats2half2_rn(a * di, b * di);
            unpack2(acc0[3], a, b); hp[3] = __floats2half2_rn(a * di, b * di);
            *reinterpret_cast<uint4*>(&Yh[g0 * 64 + w * 8]) =
                *reinterpret_cast<const uint4*>(hp);
        }
        if (g1 < n) {
            float di = PRESCALE ? __ldg(&dinv[g1]) : 1.0f;
            float a, b;
            __half2 hp[4];
            unpack2(acc1[0], a, b); hp[0] = __floats2half2_rn(a * di, b * di);
            unpack2(acc1[1], a, b); hp[1] = __floats2half2_rn(a * di, b * di);
            unpack2(acc1[2], a, b); hp[2] = __floats2half2_rn(a * di, b * di);
            unpack2(acc1[3], a, b); hp[3] = __floats2half2_rn(a * di, b * di);
            *reinterpret_cast<uint4*>(&Yh[g1 * 64 + w * 8]) =
                *reinterpret_cast<const uint4*>(hp);
        }
    }
}

// ---------------- aggregation -------------------------------------------------
// RAW:    buffer holds raw Y     -> out_i = dinv_i*(dinv_i*Y_i + sum dinv_j*Y_j)
// !RAW:   buffer holds dinv*Y    -> out_i = dinv_i*(Y'_i + sum Y'_j)
// STATS:  fused BN column stats. LOGSM: fused log_softmax, fp32 out.
// Warp per node, persistent; lane holds features (2*lane, 2*lane+1).
template <bool LOGSM, bool STATS, bool RAW>
__global__ __launch_bounds__(256)
void agg_kernel(const __half2* __restrict__ Yh,
                const int* __restrict__ rowptr, const int* __restrict__ csr,
                const float* __restrict__ dinv,
                __half2* __restrict__ outh, float2* __restrict__ outf,
                float* __restrict__ stats, int n) {
    int lane = threadIdx.x & 31;
    int wid  = (blockIdx.x * blockDim.x + threadIdx.x) >> 5;
    int nw   = (gridDim.x * blockDim.x) >> 5;
    float s0 = 0.f, q0 = 0.f, s1 = 0.f, q1 = 0.f;

    for (int i = wid; i < n; i += nw) {
        float di = __ldg(&dinv[i]);
        float2 a = __half22float2(__ldg(&Yh[i * 32 + lane]));
        if (RAW) { a.x *= di; a.y *= di; }
        int s = __ldg(&rowptr[i]);
        int e = __ldg(&rowptr[i + 1]);
        int p = s;
        for (; p + 8 <= e; p += 8) {
            int j[8];
            #pragma unroll
            for (int q = 0; q < 8; q++) j[q] = __ldg(&csr[p + q]);
            float w[8];
            if (RAW) {
                #pragma unroll
                for (int q = 0; q < 8; q++) w[q] = __ldg(&dinv[j[q]]);
            }
            float2 v[8];
            #pragma unroll
            for (int q = 0; q < 8; q++) v[q] = __half22float2(__ldg(&Yh[j[q] * 32 + lane]));
            #pragma unroll
            for (int q = 0; q < 8; q++) {
                if (RAW) {
                    a.x = fmaf(w[q], v[q].x, a.x);
                    a.y = fmaf(w[q], v[q].y, a.y);
                } else {
                    a.x += v[q].x;
                    a.y += v[q].y;
                }
            }
        }
        for (; p < e; p++) {
            int j0 = __ldg(&csr[p]);
            float2 v0 = __half22float2(__ldg(&Yh[j0 * 32 + lane]));
            if (RAW) {
                float w0 = __ldg(&dinv[j0]);
                a.x = fmaf(w0, v0.x, a.x);
                a.y = fmaf(w0, v0.y, a.y);
            } else {
                a.x += v0.x;
                a.y += v0.y;
            }
        }
        a.x *= di;
        a.y *= di;
        if (STATS) {
            s0 += a.x; q0 = fmaf(a.x, a.x, q0);
            s1 += a.y; q1 = fmaf(a.y, a.y, q1);
        }
        if (!LOGSM) {
            outh[i * 32 + lane] = __floats2half2_rn(a.x, a.y);
        } else {
            float m = fmaxf(a.x, a.y);
            #pragma unroll
            for (int o = 16; o > 0; o >>= 1)
                m = fmaxf(m, __shfl_xor_sync(0xFFFFFFFFu, m, o));
            float sum = expf(a.x - m) + expf(a.y - m);
            #pragma unroll
            for (int o = 16; o > 0; o >>= 1)
                sum += __shfl_xor_sync(0xFFFFFFFFu, sum, o);
            float lz = m + logf(sum);
            outf[i * 32 + lane] = make_float2(a.x - lz, a.y - lz);
        }
    }

    if (STATS) {
        __shared__ float4 red[256];
        red[threadIdx.x] = make_float4(s0, q0, s1, q1);
        __syncthreads();
        if (threadIdx.x < 32) {
            float4 r = red[threadIdx.x];
            #pragma unroll
            for (int w = 1; w < 8; w++) {
                float4 o = red[w * 32 + threadIdx.x];
                r.x += o.x; r.y += o.y; r.z += o.z; r.w += o.w;
            }
            atomicAdd(&stats[2 * threadIdx.x],          r.x);
            atomicAdd(&stats[64 + 2 * threadIdx.x],     r.y);
            atomicAdd(&stats[2 * threadIdx.x + 1],      r.z);
            atomicAdd(&stats[64 + 2 * threadIdx.x + 1], r.w);
        }
    }
}

// ---------------- host launcher ----------------
extern "C" void kernel_launch(void* const* d_in, const int* in_sizes, int n_in,
                              void* d_out, int out_size) {
    const float* x   = (const float*)d_in[0];
    const int*   ei  = (const int*)  d_in[1];
    const float* W1  = (const float*)d_in[2];
    const float* b1  = (const float*)d_in[3];
    const float* ga1 = (const float*)d_in[4];
    const float* be1 = (const float*)d_in[5];
    const float* W2  = (const float*)d_in[6];
    const float* b2  = (const float*)d_in[7];
    const float* ga2 = (const float*)d_in[8];
    const float* be2 = (const float*)d_in[9];
    const float* W3  = (const float*)d_in[10];
    const float* b3  = (const float*)d_in[11];
    float* out = (float*)d_out;

    int N = in_sizes[0] / 128;
    int E = in_sizes[1] / 2;
    const int* src = ei;
    const int* dst = ei + E;

    void* p;
    cudaGetSymbolAddress(&p, g_bufA);   __half* bufA  = (__half*)p;
    cudaGetSymbolAddress(&p, g_bufB);   __half* bufB  = (__half*)p;
    cudaGetSymbolAddress(&p, g_csr);    int*   csr    = (int*)p;
    cudaGetSymbolAddress(&p, g_rowptr); int*   rowptr = (int*)p;
    cudaGetSymbolAddress(&p, g_next);   int*   nextp  = (int*)p;
    cudaGetSymbolAddress(&p, g_counts); int*   counts = (int*)p;
    cudaGetSymbolAddress(&p, g_dinv);   float* dinv   = (float*)p;
    cudaGetSymbolAddress(&p, g_stat);   float* stat   = (float*)p;
    cudaGetSymbolAddress(&p, g_bsum);   int*   bsum   = (int*)p;
    cudaGetSymbolAddress(&p, g_boff);   int*   boff   = (int*)p;

    static cudaStream_t sB = nullptr;
    static cudaEvent_t  evF = nullptr, evJ = nullptr;
    if (!sB) {
        cudaStreamCreateWithFlags(&sB, cudaStreamNonBlocking);
        cudaEventCreateWithFlags(&evF, cudaEventDisableTiming);
        cudaEventCreateWithFlags(&evJ, cudaEventDisableTiming);
    }

    const int SMEM1 = (128 * 64 + 64 * 132) * 4;   // 66560 B
    const int SMEM2 = (64 * 64 + 64 * 68) * 4;     // 33792 B
    cudaFuncSetAttribute((const void*)gemm_kernel<128, false, false, float>,
                         cudaFuncAttributeMaxDynamicSharedMemorySize, SMEM1);
    cudaFuncSetAttribute((const void*)gemm_kernel<64, true, true, __half>,
                         cudaFuncAttributeMaxDynamicSharedMemorySize, SMEM2);

    int gridN  = (N + 255) / 256;
    int gridE4 = (E / 4 + 255) / 256;
    int nb     = (N + 1023) / 1024;
    int ntiles = (N + 63) / 64;
    const int G1   = 444;
    const int G2   = 592;
    const int AGGB = 1184;
    float invn = 1.0f / (float)N;

    const __half2* bufA2 = (const __half2*)bufA;
    __half2* bufB2 = (__half2*)bufB;
    float2*  out2  = (float2*)out;

    // ---- fork: CSR build on sB runs concurrently with GEMM1 (no dinv dep) ----
    cudaEventRecord(evF, 0);
    cudaStreamWaitEvent(sB, evF, 0);

    zero_kernel<<<gridN, 256, 0, sB>>>(counts, stat, N);
    count_kernel<<<gridE4, 256, 0, sB>>>(dst, counts, E);
    bsum_kernel<<<nb, 256, 0, sB>>>(counts, bsum, N);
    bscan_kernel<<<1, 128, 0, sB>>>(bsum, boff, rowptr, nb, N, E);
    scatter_scan_kernel<<<nb, 256, 0, sB>>>(counts, boff, rowptr, nextp, dinv, N);
    fill_kernel<<<gridE4, 256, 0, sB>>>(src, dst, nextp, csr, E);
    cudaEventRecord(evJ, sB);

    // layer 1: raw GEMM overlaps the CSR build
    gemm_kernel<128, false, false, float><<<G1, 256, SMEM1>>>(
        x, W1, b1, nullptr, nullptr, nullptr, invn, nullptr, bufA, N, ntiles);
    cudaStreamWaitEvent(0, evJ, 0);
    agg_kernel<false, true, true><<<AGGB, 256>>>(
        bufA2, rowptr, csr, dinv, bufB2, nullptr, stat, N);

    // layer 2
    gemm_kernel<64, true, true, __half><<<G2, 256, SMEM2>>>(
        bufB, W2, b2, stat, ga1, be1, invn, dinv, bufA, N, ntiles);
    agg_kernel<false, true, false><<<AGGB, 256>>>(
        bufA2, rowptr, csr, dinv, bufB2, nullptr, stat + 128, N);

    // layer 3 + log_softmax
    gemm_kernel<64, true, true, __half><<<G2, 256, SMEM2>>>(
        bufB, W3, b3, stat + 128, ga2, be2, invn, dinv, bufA, N, ntiles);
    agg_kernel<true, false, false><<<AGGB, 256>>>(
        bufA2, rowptr, csr, dinv, nullptr, out2, nullptr, N);
}